// round 15
// baseline (speedup 1.0000x reference)
#include <cuda_runtime.h>
#include <cuda_bf16.h>
#include <math.h>
#include <stdint.h>

#define NN 12000
#define EE 384000
#define FIN 512
#define FHID 256
#define FOUT 64
#define CAP 128                      // bucket capacity per node (mean deg 32)

// ---------------- scratch (static __device__, no allocs) ----------------
__device__ int   g_is64;
__device__ float g_dinv[NN];
__device__ int   g_fill[NN];
__device__ int   g_srcB[NN * CAP];   // bucket CSR: node c's sources at c*CAP
__device__ float g_hw[NN * FHID];    // linear output (pre-aggregation)
// split-bf16 activation buffers (reused across layers)
__device__ __nv_bfloat16 g_ah[NN * FIN], g_al[NN * FIN];
// per-layer split weight buffers (transposed: [N][K])
__device__ __nv_bfloat16 g_w1h[FHID * FIN],  g_w1l[FHID * FIN];
__device__ __nv_bfloat16 g_w2h[FHID * FHID], g_w2l[FHID * FHID];
__device__ __nv_bfloat16 g_wmh[FOUT * FHID], g_wml[FOUT * FHID];

// ---------------- helpers ----------------
__device__ __forceinline__ float fsig(float s) {
    return __fdividef(1.0f, 1.0f + __expf(-s));
}
__device__ __forceinline__ uint32_t smem_u32(const void* p) {
    uint32_t a;
    asm("{ .reg .u64 t; cvta.to.shared.u64 t, %1; cvt.u32.u64 %0, t; }" : "=r"(a) : "l"(p));
    return a;
}
__device__ __forceinline__ void ldsm4(uint32_t addr, uint32_t& r0, uint32_t& r1,
                                      uint32_t& r2, uint32_t& r3) {
    asm volatile("ldmatrix.sync.aligned.m8n8.x4.shared.b16 {%0,%1,%2,%3}, [%4];"
                 : "=r"(r0), "=r"(r1), "=r"(r2), "=r"(r3) : "r"(addr));
}
__device__ __forceinline__ void mma16816(float* c, const uint32_t* a,
                                         uint32_t b0, uint32_t b1) {
    asm volatile(
        "mma.sync.aligned.m16n8k16.row.col.f32.bf16.bf16.f32 "
        "{%0,%1,%2,%3}, {%4,%5,%6,%7}, {%8,%9}, {%0,%1,%2,%3};"
        : "+f"(c[0]), "+f"(c[1]), "+f"(c[2]), "+f"(c[3])
        : "r"(a[0]), "r"(a[1]), "r"(a[2]), "r"(a[3]), "r"(b0), "r"(b1));
}

// Load edge index element honoring detected dtype, clamped to [0, NN).
__device__ __forceinline__ int load_ei(const void* ei, long long idx) {
    int v;
    if (g_is64) v = (int)((const long long*)ei)[idx];
    else        v = ((const int*)ei)[idx];
    return min(max(v, 0), NN - 1);
}

__device__ __forceinline__ void split2(float vx, float vy,
                                       uint32_t& hp, uint32_t& lp) {
    __nv_bfloat162 h = __floats2bfloat162_rn(vx, vy);
    float2 hf = __bfloat1622float2(h);
    __nv_bfloat162 l = __floats2bfloat162_rn(vx - hf.x, vy - hf.y);
    hp = *(uint32_t*)&h;
    lp = *(uint32_t*)&l;
}

// ---------------- fused prep: init/detect + x split + W transpose-split ------
#define W1_ELEMS (FIN * FHID)
#define W2_ELEMS (FHID * FHID)
#define WM_ELEMS (FHID * FOUT)
#define W_ITEMS  (W1_ELEMS + W2_ELEMS + WM_ELEMS)
#define SPLIT4   (NN * FIN / 4)
#define PREP_ITEMS (SPLIT4 + W_ITEMS + NN)

__global__ void prep_kernel(const float4* __restrict__ x4,
                            const float* __restrict__ W1,
                            const float* __restrict__ W2,
                            const float* __restrict__ Wmu,
                            const void* ei) {
    int i = blockIdx.x * blockDim.x + threadIdx.x;
    if (i < SPLIT4) {
        float4 v = x4[i];
        uint2 hp, lp;
        split2(v.x, v.y, hp.x, lp.x);
        split2(v.z, v.w, hp.y, lp.y);
        *(uint2*)(g_ah + 4 * (size_t)i) = hp;
        *(uint2*)(g_al + 4 * (size_t)i) = lp;
    } else if (i < SPLIT4 + W_ITEMS) {
        int idx = i - SPLIT4;
        const float* W;
        __nv_bfloat16 *th, *tl;
        int K, N;
        if (idx < W1_ELEMS) {
            W = W1; th = g_w1h; tl = g_w1l; K = FIN; N = FHID;
        } else if (idx < W1_ELEMS + W2_ELEMS) {
            W = W2; th = g_w2h; tl = g_w2l; K = FHID; N = FHID; idx -= W1_ELEMS;
        } else {
            W = Wmu; th = g_wmh; tl = g_wml; K = FHID; N = FOUT;
            idx -= W1_ELEMS + W2_ELEMS;
        }
        int k = idx / N, n = idx % N;
        float v = W[idx];
        __nv_bfloat16 h = __float2bfloat16(v);
        th[n * K + k] = h;
        tl[n * K + k] = __float2bfloat16(v - __bfloat162float(h));
    } else if (i < PREP_ITEMS) {
        int n = i - SPLIT4 - W_ITEMS;
        g_fill[n] = 0;
        if (n == 0) {
            const int* w = (const int*)ei;
            bool is64 = true;
            for (int k = 1; k < 64; k += 2)
                if (w[k] != 0) { is64 = false; break; }
            g_is64 = is64 ? 1 : 0;
        }
    }
}

// ---------------- single-pass bucket CSR fill (no prescan needed) ------------
#define EQ (EE / 4)   // 96000
__global__ void fillb_kernel(const void* __restrict__ ei) {
    int t = blockIdx.x * blockDim.x + threadIdx.x;
    if (t < EQ) {
#pragma unroll
        for (int k = 0; k < 4; k++) {
            int e = t + k * EQ;
            int r = load_ei(ei, e);
            int c = load_ei(ei, (long long)EE + e);
            int p = atomicAdd(&g_fill[c], 1);
            if (p < CAP) g_srcB[c * CAP + p] = r;
        }
    }
}

__global__ void dinv_kernel() {
    int i = blockIdx.x * blockDim.x + threadIdx.x;
    if (i < NN) g_dinv[i] = rsqrtf(1.0f + (float)g_fill[i]);  // +1 self loop
}

// ---------------- split-bf16 tensor-core GEMM: C = A(M,K) . B(N,K)^T ----------
#define SA 72                       // smem row stride in bf16 (144 B)
#define MMA_SMEM (4 * 128 * SA * 2) // 73728 B

template <bool SIG>
__device__ __forceinline__ void mma_tile_body(
    const __nv_bfloat16* Ah_, const __nv_bfloat16* Al_,
    const __nv_bfloat16* Bh_, const __nv_bfloat16* Bl_,
    int M, int N, int K, int row0, int col0,
    __nv_bfloat16* sm, float c[2][8][4]) {
    uint32_t sb  = smem_u32(sm);
    uint32_t sAh = sb;
    uint32_t sAl = sb + 128 * SA * 2;
    uint32_t sBh = sb + 2 * 128 * SA * 2;
    uint32_t sBl = sb + 3 * 128 * SA * 2;
    __nv_bfloat16* pAh = sm;
    __nv_bfloat16* pAl = sm + 128 * SA;
    __nv_bfloat16* pBh = sm + 2 * 128 * SA;
    __nv_bfloat16* pBl = sm + 3 * 128 * SA;

    int tid = threadIdx.x, wid = tid >> 5, lane = tid & 31;
    int wm = wid & 3, wn = wid >> 2;

#pragma unroll
    for (int a = 0; a < 2; a++)
#pragma unroll
        for (int b = 0; b < 8; b++)
#pragma unroll
            for (int d = 0; d < 4; d++) c[a][b][d] = 0.f;

    const uint4 z4 = make_uint4(0, 0, 0, 0);
    for (int k0 = 0; k0 < K; k0 += 64) {
#pragma unroll
        for (int it = 0; it < 4; it++) {
            int v = it * 256 + tid;
            int r = v >> 3, cs = (v & 7) * 8;
            int gr = row0 + r;
            size_t ga = (size_t)gr * K + k0 + cs;
            uint4 t;
            t = (gr < M) ? *(const uint4*)(Ah_ + ga) : z4;
            *(uint4*)(pAh + r * SA + cs) = t;
            t = (gr < M) ? *(const uint4*)(Al_ + ga) : z4;
            *(uint4*)(pAl + r * SA + cs) = t;
            int gc = col0 + r;
            size_t gb = (size_t)gc * K + k0 + cs;
            t = (gc < N) ? *(const uint4*)(Bh_ + gb) : z4;
            *(uint4*)(pBh + r * SA + cs) = t;
            t = (gc < N) ? *(const uint4*)(Bl_ + gb) : z4;
            *(uint4*)(pBl + r * SA + cs) = t;
        }
        __syncthreads();

        int quad = lane >> 3, qr = lane & 7;
        int mq = (quad & 1) * 8 + qr;
        int kq = (quad >> 1) * 8;

#pragma unroll
        for (int ks = 0; ks < 64; ks += 16) {
            uint32_t aH[2][4], aL[2][4];
#pragma unroll
            for (int mt = 0; mt < 2; mt++) {
                uint32_t off = (uint32_t)((wm * 32 + mt * 16 + mq) * SA + ks + kq) * 2;
                ldsm4(sAh + off, aH[mt][0], aH[mt][1], aH[mt][2], aH[mt][3]);
                ldsm4(sAl + off, aL[mt][0], aL[mt][1], aL[mt][2], aL[mt][3]);
            }
#pragma unroll
            for (int np = 0; np < 4; np++) {
                uint32_t off = (uint32_t)((wn * 64 + np * 16 + mq) * SA + ks + kq) * 2;
                uint32_t bh[4], bl[4];
                ldsm4(sBh + off, bh[0], bh[1], bh[2], bh[3]);
                ldsm4(sBl + off, bl[0], bl[1], bl[2], bl[3]);
#pragma unroll
                for (int mt = 0; mt < 2; mt++) {
                    float* c0 = c[mt][np * 2];
                    float* c1 = c[mt][np * 2 + 1];
                    mma16816(c0, aH[mt], bh[0], bh[2]);
                    mma16816(c0, aH[mt], bl[0], bl[2]);
                    mma16816(c0, aL[mt], bh[0], bh[2]);
                    mma16816(c1, aH[mt], bh[1], bh[3]);
                    mma16816(c1, aH[mt], bl[1], bl[3]);
                    mma16816(c1, aL[mt], bh[1], bh[3]);
                }
            }
        }
        __syncthreads();
    }
    if (SIG) {
#pragma unroll
        for (int a = 0; a < 2; a++)
#pragma unroll
            for (int b = 0; b < 8; b++)
#pragma unroll
                for (int d = 0; d < 4; d++) c[a][b][d] = fsig(c[a][b][d]);
    }
}

// plain GEMM (feature layers)
__global__ void __launch_bounds__(256, 2) mma_gemm_kernel(
    const __nv_bfloat16* __restrict__ Ah_, const __nv_bfloat16* __restrict__ Al_,
    const __nv_bfloat16* __restrict__ Bh_, const __nv_bfloat16* __restrict__ Bl_,
    float* __restrict__ C, int M, int N, int K) {
    extern __shared__ __nv_bfloat16 sm[];
    int row0 = blockIdx.y * 128, col0 = blockIdx.x * 128;
    float c[2][8][4];
    mma_tile_body<false>(Ah_, Al_, Bh_, Bl_, M, N, K, row0, col0, sm, c);

    int tid = threadIdx.x, wid = tid >> 5, lane = tid & 31;
    int wm = wid & 3, wn = wid >> 2;
    int mb = row0 + wm * 32 + (lane >> 2);
    int nb = col0 + wn * 64 + (lane & 3) * 2;
#pragma unroll
    for (int mt = 0; mt < 2; mt++) {
#pragma unroll
        for (int nt = 0; nt < 8; nt++) {
            int gr = mb + mt * 16;
            int gc = nb + nt * 8;
            if (gc < N) {
                if (gr < M)     *(float2*)(C + (size_t)gr * N + gc)       = make_float2(c[mt][nt][0], c[mt][nt][1]);
                if (gr + 8 < M) *(float2*)(C + (size_t)(gr + 8) * N + gc) = make_float2(c[mt][nt][2], c[mt][nt][3]);
            }
        }
    }
}

// symmetric decoder: out = sigmoid(z z^T); lower-triangle tiles, mirrored store
__global__ void __launch_bounds__(256, 2) zzt_sym_kernel(
    const __nv_bfloat16* __restrict__ zh, const __nv_bfloat16* __restrict__ zl,
    float* __restrict__ out) {
    extern __shared__ __nv_bfloat16 sm[];
    // linear block index -> lower-triangle tile (by >= bx)
    int i = blockIdx.x;
    int by = (int)((sqrtf(8.0f * (float)i + 1.0f) - 1.0f) * 0.5f);
    while ((by + 1) * (by + 2) / 2 <= i) by++;
    while (by * (by + 1) / 2 > i) by--;
    int bx = i - by * (by + 1) / 2;
    int row0 = by * 128, col0 = bx * 128;

    float c[2][8][4];
    mma_tile_body<true>(zh, zl, zh, zl, NN, NN, FOUT, row0, col0, sm, c);

    int tid = threadIdx.x, wid = tid >> 5, lane = tid & 31;
    int wm = wid & 3, wn = wid >> 2;
    int mb = row0 + wm * 32 + (lane >> 2);
    int nb = col0 + wn * 64 + (lane & 3) * 2;

    // direct store of tile (by, bx)
#pragma unroll
    for (int mt = 0; mt < 2; mt++) {
#pragma unroll
        for (int nt = 0; nt < 8; nt++) {
            int gr = mb + mt * 16;
            int gc = nb + nt * 8;
            if (gc < NN) {
                if (gr < NN)     *(float2*)(out + (size_t)gr * NN + gc)       = make_float2(c[mt][nt][0], c[mt][nt][1]);
                if (gr + 8 < NN) *(float2*)(out + (size_t)(gr + 8) * NN + gc) = make_float2(c[mt][nt][2], c[mt][nt][3]);
            }
        }
    }

    if (bx == by) return;

    // mirrored tile (bx, by): transpose through smem stage, coalesced STG
    float* stage = reinterpret_cast<float*>(sm);   // 128 x 132 fp32 = 67584 B
    __syncthreads();                                // operand tiles dead; reuse
    int rl0 = wm * 32 + (lane >> 2);
    int cl0 = wn * 64 + (lane & 3) * 2;
#pragma unroll
    for (int mt = 0; mt < 2; mt++) {
#pragma unroll
        for (int nt = 0; nt < 8; nt++) {
            int rl = rl0 + mt * 16;
            int cl = cl0 + nt * 8;
            stage[cl * 132 + rl]           = c[mt][nt][0];
            stage[(cl + 1) * 132 + rl]     = c[mt][nt][1];
            stage[cl * 132 + rl + 8]       = c[mt][nt][2];
            stage[(cl + 1) * 132 + rl + 8] = c[mt][nt][3];
        }
    }
    __syncthreads();
#pragma unroll
    for (int it = 0; it < 16; it++) {
        int idx = it * 256 + tid;
        int rr = idx >> 5;            // mirror row within tile
        int cc = (idx & 31) * 4;      // mirror col within tile
        int gr = col0 + rr;           // < NN guaranteed (bx < by)
        int gc = row0 + cc;
        float4 v = *(float4*)&stage[rr * 132 + cc];
        float* p = out + (size_t)gr * NN + gc;
        if (gc + 3 < NN) *(float4*)p = v;
        else {
            if (gc < NN)     p[0] = v.x;
            if (gc + 1 < NN) p[1] = v.y;
            if (gc + 2 < NN) p[2] = v.z;
            if (gc + 3 < NN) p[3] = v.w;
        }
    }
}

// ---------------- GCN aggregation (bucket CSR, warp per node) -----------------
// out[c] = dinv[c] * ( sum_r dinv[r]*hw[r]  +  dinv[c]*hw[c] )
template <int F, bool RELU>
__global__ void aggregate_bf16_kernel(const float* __restrict__ hw,
                                      const float* __restrict__ bias,
                                      __nv_bfloat16* __restrict__ oh,
                                      __nv_bfloat16* __restrict__ ol) {
    int gw   = (blockIdx.x * blockDim.x + threadIdx.x) >> 5;
    int lane = threadIdx.x & 31;
    if (gw >= NN) return;
    constexpr int NC = F / 64;             // float2 chunks per lane (4 or 1)
    float2 acc[NC];
    float dc = g_dinv[gw];
    {
        const float2* hr = (const float2*)(hw + (size_t)gw * F) + lane;
#pragma unroll
        for (int j = 0; j < NC; j++) {
            float2 v = hr[j * 32];
            acc[j].x = dc * v.x;
            acc[j].y = dc * v.y;
        }
    }
    int cnt = min(g_fill[gw], CAP);
    const int* sp = g_srcB + gw * CAP;
    int p = 0;
    for (; p + 1 < cnt; p += 2) {
        int r0 = sp[p], r1 = sp[p + 1];
        float w0 = g_dinv[r0], w1 = g_dinv[r1];
        const float2* h0 = (const float2*)(hw + (size_t)r0 * F) + lane;
        const float2* h1 = (const float2*)(hw + (size_t)r1 * F) + lane;
#pragma unroll
        for (int j = 0; j < NC; j++) {
            float2 a = h0[j * 32];
            float2 b = h1[j * 32];
            acc[j].x += w0 * a.x + w1 * b.x;
            acc[j].y += w0 * a.y + w1 * b.y;
        }
    }
    if (p < cnt) {
        int r0 = sp[p];
        float w0 = g_dinv[r0];
        const float2* h0 = (const float2*)(hw + (size_t)r0 * F) + lane;
#pragma unroll
        for (int j = 0; j < NC; j++) {
            float2 a = h0[j * 32];
            acc[j].x += w0 * a.x;
            acc[j].y += w0 * a.y;
        }
    }
#pragma unroll
    for (int j = 0; j < NC; j++) {
        int f = j * 64 + lane * 2;
        float vx = dc * acc[j].x + bias[f];
        float vy = dc * acc[j].y + bias[f + 1];
        if (RELU) { vx = fmaxf(vx, 0.f); vy = fmaxf(vy, 0.f); }
        __nv_bfloat16 hx = __float2bfloat16(vx);
        __nv_bfloat16 hy = __float2bfloat16(vy);
        __nv_bfloat162 hp, lp;
        hp.x = hx; hp.y = hy;
        lp.x = __float2bfloat16(vx - __bfloat162float(hx));
        lp.y = __float2bfloat16(vy - __bfloat162float(hy));
        *(__nv_bfloat162*)(oh + (size_t)gw * F + f) = hp;
        *(__nv_bfloat162*)(ol + (size_t)gw * F + f) = lp;
    }
}

// ---------------- launch (single stream; graph-capture safe) ----------------
extern "C" void kernel_launch(void* const* d_in, const int* in_sizes, int n_in,
                              void* d_out, int out_size) {
    const float* x   = (const float*)d_in[0];
    const void*  ei  = (const void*)d_in[1];
    const float* W1  = (const float*)d_in[2];
    const float* b1  = (const float*)d_in[3];
    const float* W2  = (const float*)d_in[4];
    const float* b2  = (const float*)d_in[5];
    const float* Wmu = (const float*)d_in[6];
    const float* bmu = (const float*)d_in[7];
    float*       out = (float*)d_out;
    (void)in_sizes; (void)n_in; (void)out_size;

    float* hw;
    __nv_bfloat16 *ah, *al;
    __nv_bfloat16 *w1h, *w1l, *w2h, *w2l, *wmh, *wml;
    cudaGetSymbolAddress((void**)&hw,  g_hw);
    cudaGetSymbolAddress((void**)&ah,  g_ah);
    cudaGetSymbolAddress((void**)&al,  g_al);
    cudaGetSymbolAddress((void**)&w1h, g_w1h);
    cudaGetSymbolAddress((void**)&w1l, g_w1l);
    cudaGetSymbolAddress((void**)&w2h, g_w2h);
    cudaGetSymbolAddress((void**)&w2l, g_w2l);
    cudaGetSymbolAddress((void**)&wmh, g_wmh);
    cudaGetSymbolAddress((void**)&wml, g_wml);

    cudaFuncSetAttribute(mma_gemm_kernel,
                         cudaFuncAttributeMaxDynamicSharedMemorySize, MMA_SMEM);
    cudaFuncSetAttribute(zzt_sym_kernel,
                         cudaFuncAttributeMaxDynamicSharedMemorySize, MMA_SMEM);

    // prep (init/detect + x split + W split), bucket CSR fill, dinv
    prep_kernel<<<(PREP_ITEMS + 255) / 256, 256>>>(
        (const float4*)x, W1, W2, Wmu, ei);
    fillb_kernel<<<(EQ + 255) / 256, 256>>>(ei);
    dinv_kernel<<<(NN + 255) / 256, 256>>>();

    const int aggBlocks = (NN * 32 + 255) / 256;
    const int mTiles = (NN + 127) / 128;  // 94

    // layer 1
    mma_gemm_kernel<<<dim3(FHID / 128, mTiles), 256, MMA_SMEM>>>(
        ah, al, w1h, w1l, hw, NN, FHID, FIN);
    aggregate_bf16_kernel<FHID, true><<<aggBlocks, 256>>>(hw, b1, ah, al);

    // layer 2
    mma_gemm_kernel<<<dim3(FHID / 128, mTiles), 256, MMA_SMEM>>>(
        ah, al, w2h, w2l, hw, NN, FHID, FHID);
    aggregate_bf16_kernel<FHID, true><<<aggBlocks, 256>>>(hw, b2, ah, al);

    // mu layer (logstd unused: z = mu in eval)
    mma_gemm_kernel<<<dim3(1, mTiles), 256, MMA_SMEM>>>(
        ah, al, wmh, wml, hw, NN, FOUT, FHID);
    aggregate_bf16_kernel<FOUT, false><<<aggBlocks, 256>>>(hw, bmu, ah, al);

    // decoder: out = sigmoid(z z^T), symmetric lower-triangle + mirror
    const int triTiles = mTiles * (mTiles + 1) / 2;  // 4465
    zzt_sym_kernel<<<triTiles, 256, MMA_SMEM>>>(ah, al, out);
}

// round 17
// speedup vs baseline: 1.5150x; 1.5150x over previous
#include <cuda_runtime.h>
#include <cuda_bf16.h>
#include <math.h>
#include <stdint.h>

#define NN 12000
#define EE 384000
#define FIN 512
#define FHID 256
#define FOUT 64

// ---------------- scratch (static __device__, no allocs) ----------------
__device__ int   g_is64;
__device__ int   g_cursor;
__device__ float g_deg[NN];
__device__ float g_dinv[NN];
__device__ int   g_rs[NN];          // CSR segment start (unordered layout)
__device__ int   g_fill[NN];
__device__ int   g_src[EE];
__device__ float g_w[EE];
__device__ float g_hw[NN * FHID];   // linear output (pre-aggregation)
// split-bf16 activation buffers (reused across layers)
__device__ __nv_bfloat16 g_ah[NN * FIN], g_al[NN * FIN];
// per-layer split weight buffers (transposed: [N][K])
__device__ __nv_bfloat16 g_w1h[FHID * FIN],  g_w1l[FHID * FIN];
__device__ __nv_bfloat16 g_w2h[FHID * FHID], g_w2l[FHID * FHID];
__device__ __nv_bfloat16 g_wmh[FOUT * FHID], g_wml[FOUT * FHID];

// ---------------- helpers ----------------
__device__ __forceinline__ float fsig(float s) {
    return __fdividef(1.0f, 1.0f + __expf(-s));
}
__device__ __forceinline__ uint32_t smem_u32(const void* p) {
    uint32_t a;
    asm("{ .reg .u64 t; cvta.to.shared.u64 t, %1; cvt.u32.u64 %0, t; }" : "=r"(a) : "l"(p));
    return a;
}
__device__ __forceinline__ void ldsm4(uint32_t addr, uint32_t& r0, uint32_t& r1,
                                      uint32_t& r2, uint32_t& r3) {
    asm volatile("ldmatrix.sync.aligned.m8n8.x4.shared.b16 {%0,%1,%2,%3}, [%4];"
                 : "=r"(r0), "=r"(r1), "=r"(r2), "=r"(r3) : "r"(addr));
}
__device__ __forceinline__ void mma16816(float* c, const uint32_t* a,
                                         uint32_t b0, uint32_t b1) {
    asm volatile(
        "mma.sync.aligned.m16n8k16.row.col.f32.bf16.bf16.f32 "
        "{%0,%1,%2,%3}, {%4,%5,%6,%7}, {%8,%9}, {%0,%1,%2,%3};"
        : "+f"(c[0]), "+f"(c[1]), "+f"(c[2]), "+f"(c[3])
        : "r"(a[0]), "r"(a[1]), "r"(a[2]), "r"(a[3]), "r"(b0), "r"(b1));
}

// Load edge index element honoring detected dtype, clamped to [0, NN).
__device__ __forceinline__ int load_ei(const void* ei, long long idx) {
    int v;
    if (g_is64) v = (int)((const long long*)ei)[idx];
    else        v = ((const int*)ei)[idx];
    return min(max(v, 0), NN - 1);
}

__device__ __forceinline__ void split2(float vx, float vy,
                                       uint32_t& hp, uint32_t& lp) {
    __nv_bfloat162 h = __floats2bfloat162_rn(vx, vy);
    float2 hf = __bfloat1622float2(h);
    __nv_bfloat162 l = __floats2bfloat162_rn(vx - hf.x, vy - hf.y);
    hp = *(uint32_t*)&h;
    lp = *(uint32_t*)&l;
}

// ---------------- fused prep: init/detect + x split + W transpose-split ------
#define W1_ELEMS (FIN * FHID)
#define W2_ELEMS (FHID * FHID)
#define WM_ELEMS (FHID * FOUT)
#define W_ITEMS  (W1_ELEMS + W2_ELEMS + WM_ELEMS)
#define SPLIT4   (NN * FIN / 4)
#define PREP_ITEMS (SPLIT4 + W_ITEMS + NN)

__global__ void prep_kernel(const float4* __restrict__ x4,
                            const float* __restrict__ W1,
                            const float* __restrict__ W2,
                            const float* __restrict__ Wmu,
                            const void* ei) {
    int i = blockIdx.x * blockDim.x + threadIdx.x;
    if (i < SPLIT4) {
        float4 v = x4[i];
        uint2 hp, lp;
        split2(v.x, v.y, hp.x, lp.x);
        split2(v.z, v.w, hp.y, lp.y);
        *(uint2*)(g_ah + 4 * (size_t)i) = hp;
        *(uint2*)(g_al + 4 * (size_t)i) = lp;
    } else if (i < SPLIT4 + W_ITEMS) {
        int idx = i - SPLIT4;
        const float* W;
        __nv_bfloat16 *th, *tl;
        int K, N;
        if (idx < W1_ELEMS) {
            W = W1; th = g_w1h; tl = g_w1l; K = FIN; N = FHID;
        } else if (idx < W1_ELEMS + W2_ELEMS) {
            W = W2; th = g_w2h; tl = g_w2l; K = FHID; N = FHID; idx -= W1_ELEMS;
        } else {
            W = Wmu; th = g_wmh; tl = g_wml; K = FHID; N = FOUT;
            idx -= W1_ELEMS + W2_ELEMS;
        }
        int k = idx / N, n = idx % N;
        float v = W[idx];
        __nv_bfloat16 h = __float2bfloat16(v);
        th[n * K + k] = h;
        tl[n * K + k] = __float2bfloat16(v - __bfloat162float(h));
    } else if (i < PREP_ITEMS) {
        int n = i - SPLIT4 - W_ITEMS;
        g_deg[n] = 1.0f;     // self loop
        g_fill[n] = 0;
        if (n == 0) {
            g_cursor = 0;
            const int* w = (const int*)ei;
            bool is64 = true;
            for (int k = 1; k < 64; k += 2)
                if (w[k] != 0) { is64 = false; break; }
            g_is64 = is64 ? 1 : 0;
        }
    }
}

// ---------------- degree count: 4 independent edges per thread ----------------
#define EQ (EE / 4)   // 96000
__global__ void count_kernel(const void* __restrict__ ei) {
    int t = blockIdx.x * blockDim.x + threadIdx.x;
    if (t < EQ) {
#pragma unroll
        for (int k = 0; k < 4; k++) {
            int e = t + k * EQ;
            atomicAdd(&g_deg[load_ei(ei, (long long)EE + e)], 1.0f);
        }
    }
}

__global__ void dinvoff_kernel() {
    int i = blockIdx.x * blockDim.x + threadIdx.x;
    if (i < NN) {
        float dg = g_deg[i];
        g_dinv[i] = rsqrtf(dg);
        int d = (int)(dg + 0.5f) - 1;   // in-degree (minus self loop)
        g_rs[i] = atomicAdd(&g_cursor, d);
    }
}

__global__ void fill_kernel(const void* __restrict__ ei) {
    int t = blockIdx.x * blockDim.x + threadIdx.x;
    if (t < EQ) {
#pragma unroll
        for (int k = 0; k < 4; k++) {
            int e = t + k * EQ;
            int r = load_ei(ei, e);
            int c = load_ei(ei, (long long)EE + e);
            int p = g_rs[c] + atomicAdd(&g_fill[c], 1);
            if (p < EE) {
                g_src[p] = r;
                g_w[p]   = g_dinv[r] * g_dinv[c];
            }
        }
    }
}

// ---------------- decoder tile body (proven 128x128, SIG) --------------------
#define SA 72                       // smem row stride in bf16 (144 B)
#define MMA_SMEM (4 * 128 * SA * 2) // 73728 B

__device__ __forceinline__ void mma_tile_body_sig(
    const __nv_bfloat16* Ah_, const __nv_bfloat16* Al_,
    const __nv_bfloat16* Bh_, const __nv_bfloat16* Bl_,
    int M, int N, int K, int row0, int col0,
    __nv_bfloat16* sm, float c[2][8][4]) {
    uint32_t sb  = smem_u32(sm);
    uint32_t sAh = sb;
    uint32_t sAl = sb + 128 * SA * 2;
    uint32_t sBh = sb + 2 * 128 * SA * 2;
    uint32_t sBl = sb + 3 * 128 * SA * 2;
    __nv_bfloat16* pAh = sm;
    __nv_bfloat16* pAl = sm + 128 * SA;
    __nv_bfloat16* pBh = sm + 2 * 128 * SA;
    __nv_bfloat16* pBl = sm + 3 * 128 * SA;

    int tid = threadIdx.x, wid = tid >> 5, lane = tid & 31;
    int wm = wid & 3, wn = wid >> 2;

#pragma unroll
    for (int a = 0; a < 2; a++)
#pragma unroll
        for (int b = 0; b < 8; b++)
#pragma unroll
            for (int d = 0; d < 4; d++) c[a][b][d] = 0.f;

    const uint4 z4 = make_uint4(0, 0, 0, 0);
    for (int k0 = 0; k0 < K; k0 += 64) {
#pragma unroll
        for (int it = 0; it < 4; it++) {
            int v = it * 256 + tid;
            int r = v >> 3, cs = (v & 7) * 8;
            int gr = row0 + r;
            size_t ga = (size_t)gr * K + k0 + cs;
            uint4 t;
            t = (gr < M) ? *(const uint4*)(Ah_ + ga) : z4;
            *(uint4*)(pAh + r * SA + cs) = t;
            t = (gr < M) ? *(const uint4*)(Al_ + ga) : z4;
            *(uint4*)(pAl + r * SA + cs) = t;
            int gc = col0 + r;
            size_t gb = (size_t)gc * K + k0 + cs;
            t = (gc < N) ? *(const uint4*)(Bh_ + gb) : z4;
            *(uint4*)(pBh + r * SA + cs) = t;
            t = (gc < N) ? *(const uint4*)(Bl_ + gb) : z4;
            *(uint4*)(pBl + r * SA + cs) = t;
        }
        __syncthreads();

        int quad = lane >> 3, qr = lane & 7;
        int mq = (quad & 1) * 8 + qr;
        int kq = (quad >> 1) * 8;

#pragma unroll
        for (int ks = 0; ks < 64; ks += 16) {
            uint32_t aH[2][4], aL[2][4];
#pragma unroll
            for (int mt = 0; mt < 2; mt++) {
                uint32_t off = (uint32_t)((wm * 32 + mt * 16 + mq) * SA + ks + kq) * 2;
                ldsm4(sAh + off, aH[mt][0], aH[mt][1], aH[mt][2], aH[mt][3]);
                ldsm4(sAl + off, aL[mt][0], aL[mt][1], aL[mt][2], aL[mt][3]);
            }
#pragma unroll
            for (int np = 0; np < 4; np++) {
                uint32_t off = (uint32_t)((wn * 64 + np * 16 + mq) * SA + ks + kq) * 2;
                uint32_t bh[4], bl[4];
                ldsm4(sBh + off, bh[0], bh[1], bh[2], bh[3]);
                ldsm4(sBl + off, bl[0], bl[1], bl[2], bl[3]);
#pragma unroll
                for (int mt = 0; mt < 2; mt++) {
                    float* c0 = c[mt][np * 2];
                    float* c1 = c[mt][np * 2 + 1];
                    mma16816(c0, aH[mt], bh[0], bh[2]);
                    mma16816(c0, aH[mt], bl[0], bl[2]);
                    mma16816(c0, aL[mt], bh[0], bh[2]);
                    mma16816(c1, aH[mt], bh[1], bh[3]);
                    mma16816(c1, aH[mt], bl[1], bl[3]);
                    mma16816(c1, aL[mt], bh[1], bh[3]);
                }
            }
        }
        __syncthreads();
    }
#pragma unroll
    for (int a = 0; a < 2; a++)
#pragma unroll
        for (int b = 0; b < 8; b++)
#pragma unroll
            for (int d = 0; d < 4; d++) c[a][b][d] = fsig(c[a][b][d]);
}

// ---------------- feature GEMM: 64(M) x 128(N) tiles for wave balance --------
// grid.y = ceil(M/64), grid.x = ceil(N/128). Warp grid 2(M) x 4(N), warp 32x32.
#define G64_SMEM ((64 + 64 + 128 + 128) * SA * 2)   // 55296 B

__global__ void __launch_bounds__(256, 3) mma_gemm64_kernel(
    const __nv_bfloat16* __restrict__ Ah_, const __nv_bfloat16* __restrict__ Al_,
    const __nv_bfloat16* __restrict__ Bh_, const __nv_bfloat16* __restrict__ Bl_,
    float* __restrict__ C, int M, int N, int K) {
    extern __shared__ __nv_bfloat16 sm[];
    uint32_t sb  = smem_u32(sm);
    uint32_t sAh = sb;
    uint32_t sAl = sb + 64 * SA * 2;
    uint32_t sBh = sb + 2 * 64 * SA * 2;
    uint32_t sBl = sb + 2 * 64 * SA * 2 + 128 * SA * 2;
    __nv_bfloat16* pAh = sm;
    __nv_bfloat16* pAl = sm + 64 * SA;
    __nv_bfloat16* pBh = sm + 2 * 64 * SA;
    __nv_bfloat16* pBl = sm + 2 * 64 * SA + 128 * SA;

    int tid = threadIdx.x, wid = tid >> 5, lane = tid & 31;
    int row0 = blockIdx.y * 64, col0 = blockIdx.x * 128;
    int wm = wid & 1, wn = wid >> 1;   // 2(M) x 4(N)

    float c[2][4][4];
#pragma unroll
    for (int a = 0; a < 2; a++)
#pragma unroll
        for (int b = 0; b < 4; b++)
#pragma unroll
            for (int d = 0; d < 4; d++) c[a][b][d] = 0.f;

    const uint4 z4 = make_uint4(0, 0, 0, 0);
    for (int k0 = 0; k0 < K; k0 += 64) {
#pragma unroll
        for (int it = 0; it < 2; it++) {          // A: 64 rows x 8 segs = 512
            int v = it * 256 + tid;
            int r = v >> 3, cs = (v & 7) * 8;
            int gr = row0 + r;
            size_t ga = (size_t)gr * K + k0 + cs;
            uint4 t;
            t = (gr < M) ? *(const uint4*)(Ah_ + ga) : z4;
            *(uint4*)(pAh + r * SA + cs) = t;
            t = (gr < M) ? *(const uint4*)(Al_ + ga) : z4;
            *(uint4*)(pAl + r * SA + cs) = t;
        }
#pragma unroll
        for (int it = 0; it < 4; it++) {          // B: 128 rows x 8 segs = 1024
            int v = it * 256 + tid;
            int r = v >> 3, cs = (v & 7) * 8;
            int gc = col0 + r;
            size_t gb = (size_t)gc * K + k0 + cs;
            uint4 t;
            t = (gc < N) ? *(const uint4*)(Bh_ + gb) : z4;
            *(uint4*)(pBh + r * SA + cs) = t;
            t = (gc < N) ? *(const uint4*)(Bl_ + gb) : z4;
            *(uint4*)(pBl + r * SA + cs) = t;
        }
        __syncthreads();

        int quad = lane >> 3, qr = lane & 7;
        int mq = (quad & 1) * 8 + qr;
        int kq = (quad >> 1) * 8;

#pragma unroll
        for (int ks = 0; ks < 64; ks += 16) {
            uint32_t aH[2][4], aL[2][4];
#pragma unroll
            for (int mt = 0; mt < 2; mt++) {
                uint32_t off = (uint32_t)((wm * 32 + mt * 16 + mq) * SA + ks + kq) * 2;
                ldsm4(sAh + off, aH[mt][0], aH[mt][1], aH[mt][2], aH[mt][3]);
                ldsm4(sAl + off, aL[mt][0], aL[mt][1], aL[mt][2], aL[mt][3]);
            }
#pragma unroll
            for (int np = 0; np < 2; np++) {
                uint32_t off = (uint32_t)((wn * 32 + np * 16 + mq) * SA + ks + kq) * 2;
                uint32_t bh[4], bl[4];
                ldsm4(sBh + off, bh[0], bh[1], bh[2], bh[3]);
                ldsm4(sBl + off, bl[0], bl[1], bl[2], bl[3]);
#pragma unroll
                for (int mt = 0; mt < 2; mt++) {
                    float* c0 = c[mt][np * 2];
                    float* c1 = c[mt][np * 2 + 1];
                    mma16816(c0, aH[mt], bh[0], bh[2]);
                    mma16816(c0, aH[mt], bl[0], bl[2]);
                    mma16816(c0, aL[mt], bh[0], bh[2]);
                    mma16816(c1, aH[mt], bh[1], bh[3]);
                    mma16816(c1, aH[mt], bl[1], bl[3]);
                    mma16816(c1, aL[mt], bh[1], bh[3]);
                }
            }
        }
        __syncthreads();
    }

    int mb = row0 + wm * 32 + (lane >> 2);
    int nb = col0 + wn * 32 + (lane & 3) * 2;
#pragma unroll
    for (int mt = 0; mt < 2; mt++) {
#pragma unroll
        for (int nt = 0; nt < 4; nt++) {
            int gr = mb + mt * 16;
            int gc = nb + nt * 8;
            if (gc < N) {
                if (gr < M)     *(float2*)(C + (size_t)gr * N + gc)       = make_float2(c[mt][nt][0], c[mt][nt][1]);
                if (gr + 8 < M) *(float2*)(C + (size_t)(gr + 8) * N + gc) = make_float2(c[mt][nt][2], c[mt][nt][3]);
            }
        }
    }
}

// symmetric decoder: out = sigmoid(z z^T); lower-triangle tiles, mirrored store
__global__ void __launch_bounds__(256, 2) zzt_sym_kernel(
    const __nv_bfloat16* __restrict__ zh, const __nv_bfloat16* __restrict__ zl,
    float* __restrict__ out) {
    extern __shared__ __nv_bfloat16 sm[];
    int i = blockIdx.x;
    int by = (int)((sqrtf(8.0f * (float)i + 1.0f) - 1.0f) * 0.5f);
    while ((by + 1) * (by + 2) / 2 <= i) by++;
    while (by * (by + 1) / 2 > i) by--;
    int bx = i - by * (by + 1) / 2;
    int row0 = by * 128, col0 = bx * 128;

    float c[2][8][4];
    mma_tile_body_sig(zh, zl, zh, zl, NN, NN, FOUT, row0, col0, sm, c);

    int tid = threadIdx.x, wid = tid >> 5, lane = tid & 31;
    int wm = wid & 3, wn = wid >> 2;
    int mb = row0 + wm * 32 + (lane >> 2);
    int nb = col0 + wn * 64 + (lane & 3) * 2;

#pragma unroll
    for (int mt = 0; mt < 2; mt++) {
#pragma unroll
        for (int nt = 0; nt < 8; nt++) {
            int gr = mb + mt * 16;
            int gc = nb + nt * 8;
            if (gc < NN) {
                if (gr < NN)     *(float2*)(out + (size_t)gr * NN + gc)       = make_float2(c[mt][nt][0], c[mt][nt][1]);
                if (gr + 8 < NN) *(float2*)(out + (size_t)(gr + 8) * NN + gc) = make_float2(c[mt][nt][2], c[mt][nt][3]);
            }
        }
    }

    if (bx == by) return;

    float* stage = reinterpret_cast<float*>(sm);   // 128 x 132 fp32 = 67584 B
    __syncthreads();
    int rl0 = wm * 32 + (lane >> 2);
    int cl0 = wn * 64 + (lane & 3) * 2;
#pragma unroll
    for (int mt = 0; mt < 2; mt++) {
#pragma unroll
        for (int nt = 0; nt < 8; nt++) {
            int rl = rl0 + mt * 16;
            int cl = cl0 + nt * 8;
            stage[cl * 132 + rl]           = c[mt][nt][0];
            stage[(cl + 1) * 132 + rl]     = c[mt][nt][1];
            stage[cl * 132 + rl + 8]       = c[mt][nt][2];
            stage[(cl + 1) * 132 + rl + 8] = c[mt][nt][3];
        }
    }
    __syncthreads();
#pragma unroll
    for (int it = 0; it < 16; it++) {
        int idx = it * 256 + tid;
        int rr = idx >> 5;
        int cc = (idx & 31) * 4;
        int gr = col0 + rr;
        int gc = row0 + cc;
        float4 v = *(float4*)&stage[rr * 132 + cc];
        float* p = out + (size_t)gr * NN + gc;
        if (gc + 3 < NN) *(float4*)p = v;
        else {
            if (gc < NN)     p[0] = v.x;
            if (gc + 1 < NN) p[1] = v.y;
            if (gc + 2 < NN) p[2] = v.z;
            if (gc + 3 < NN) p[3] = v.w;
        }
    }
}

// ---------------- GCN aggregation (CSR by destination, warp per node) ----------
template <int F, bool RELU>
__global__ void aggregate_bf16_kernel(const float* __restrict__ hw,
                                      const float* __restrict__ bias,
                                      __nv_bfloat16* __restrict__ oh,
                                      __nv_bfloat16* __restrict__ ol) {
    int gw   = (blockIdx.x * blockDim.x + threadIdx.x) >> 5;
    int lane = threadIdx.x & 31;
    if (gw >= NN) return;
    constexpr int NC = F / 64;             // float2 chunks per lane (4 or 1)
    float2 acc[NC];
    float d = g_dinv[gw];
    float selfw = d * d;
    {
        const float2* hr = (const float2*)(hw + (size_t)gw * F) + lane;
#pragma unroll
        for (int j = 0; j < NC; j++) {
            float2 v = hr[j * 32];
            acc[j].x = selfw * v.x;
            acc[j].y = selfw * v.y;
        }
    }
    int s = g_rs[gw];
    int e = s + ((int)(g_deg[gw] + 0.5f) - 1);
    int p = s;
    for (; p + 1 < e; p += 2) {
        int r0 = g_src[p], r1 = g_src[p + 1];
        float w0 = g_w[p], w1 = g_w[p + 1];
        const float2* h0 = (const float2*)(hw + (size_t)r0 * F) + lane;
        const float2* h1 = (const float2*)(hw + (size_t)r1 * F) + lane;
#pragma unroll
        for (int j = 0; j < NC; j++) {
            float2 a = h0[j * 32];
            float2 b = h1[j * 32];
            acc[j].x += w0 * a.x + w1 * b.x;
            acc[j].y += w0 * a.y + w1 * b.y;
        }
    }
    if (p < e) {
        int r0 = g_src[p];
        float w0 = g_w[p];
        const float2* h0 = (const float2*)(hw + (size_t)r0 * F) + lane;
#pragma unroll
        for (int j = 0; j < NC; j++) {
            float2 a = h0[j * 32];
            acc[j].x += w0 * a.x;
            acc[j].y += w0 * a.y;
        }
    }
#pragma unroll
    for (int j = 0; j < NC; j++) {
        int f = j * 64 + lane * 2;
        float vx = acc[j].x + bias[f];
        float vy = acc[j].y + bias[f + 1];
        if (RELU) { vx = fmaxf(vx, 0.f); vy = fmaxf(vy, 0.f); }
        __nv_bfloat16 hx = __float2bfloat16(vx);
        __nv_bfloat16 hy = __float2bfloat16(vy);
        __nv_bfloat162 hp, lp;
        hp.x = hx; hp.y = hy;
        lp.x = __float2bfloat16(vx - __bfloat162float(hx));
        lp.y = __float2bfloat16(vy - __bfloat162float(hy));
        *(__nv_bfloat162*)(oh + (size_t)gw * F + f) = hp;
        *(__nv_bfloat162*)(ol + (size_t)gw * F + f) = lp;
    }
}

// ---------------- launch (single stream; graph-capture safe) ----------------
extern "C" void kernel_launch(void* const* d_in, const int* in_sizes, int n_in,
                              void* d_out, int out_size) {
    const float* x   = (const float*)d_in[0];
    const void*  ei  = (const void*)d_in[1];
    const float* W1  = (const float*)d_in[2];
    const float* b1  = (const float*)d_in[3];
    const float* W2  = (const float*)d_in[4];
    const float* b2  = (const float*)d_in[5];
    const float* Wmu = (const float*)d_in[6];
    const float* bmu = (const float*)d_in[7];
    float*       out = (float*)d_out;
    (void)in_sizes; (void)n_in; (void)out_size;

    float* hw;
    __nv_bfloat16 *ah, *al;
    __nv_bfloat16 *w1h, *w1l, *w2h, *w2l, *wmh, *wml;
    cudaGetSymbolAddress((void**)&hw,  g_hw);
    cudaGetSymbolAddress((void**)&ah,  g_ah);
    cudaGetSymbolAddress((void**)&al,  g_al);
    cudaGetSymbolAddress((void**)&w1h, g_w1h);
    cudaGetSymbolAddress((void**)&w1l, g_w1l);
    cudaGetSymbolAddress((void**)&w2h, g_w2h);
    cudaGetSymbolAddress((void**)&w2l, g_w2l);
    cudaGetSymbolAddress((void**)&wmh, g_wmh);
    cudaGetSymbolAddress((void**)&wml, g_wml);

    cudaFuncSetAttribute(mma_gemm64_kernel,
                         cudaFuncAttributeMaxDynamicSharedMemorySize, G64_SMEM);
    cudaFuncSetAttribute(zzt_sym_kernel,
                         cudaFuncAttributeMaxDynamicSharedMemorySize, MMA_SMEM);

    // fused prep (init/detect + x split + W split) and graph build
    prep_kernel<<<(PREP_ITEMS + 255) / 256, 256>>>(
        (const float4*)x, W1, W2, Wmu, ei);
    count_kernel<<<(EQ + 255) / 256, 256>>>(ei);
    dinvoff_kernel<<<(NN + 255) / 256, 256>>>();
    fill_kernel<<<(EQ + 255) / 256, 256>>>(ei);

    const int aggBlocks = (NN * 32 + 255) / 256;
    const int m64Tiles = (NN + 63) / 64;   // 188
    const int mTiles = (NN + 127) / 128;   // 94

    // layer 1
    mma_gemm64_kernel<<<dim3(FHID / 128, m64Tiles), 256, G64_SMEM>>>(
        ah, al, w1h, w1l, hw, NN, FHID, FIN);
    aggregate_bf16_kernel<FHID, true><<<aggBlocks, 256>>>(hw, b1, ah, al);

    // layer 2
    mma_gemm64_kernel<<<dim3(FHID / 128, m64Tiles), 256, G64_SMEM>>>(
        ah, al, w2h, w2l, hw, NN, FHID, FHID);
    aggregate_bf16_kernel<FHID, true><<<aggBlocks, 256>>>(hw, b2, ah, al);

    // mu layer (logstd unused: z = mu in eval)
    mma_gemm64_kernel<<<dim3(1, m64Tiles), 256, G64_SMEM>>>(
        ah, al, wmh, wml, hw, NN, FOUT, FHID);
    aggregate_bf16_kernel<FOUT, false><<<aggBlocks, 256>>>(hw, bmu, ah, al);

    // decoder: out = sigmoid(z z^T), symmetric lower-triangle + mirror
    const int triTiles = mTiles * (mTiles + 1) / 2;  // 4465
    zzt_sym_kernel<<<triTiles, 256, MMA_SMEM>>>(ah, al, out);
}